// round 1
// baseline (speedup 1.0000x reference)
#include <cuda_runtime.h>

// Problem dims (fixed by the dataset)
#define BATCH 8
#define TLEN  4096
#define IDIM  1024
#define NDIM  64
#define BT    (BATCH * TLEN)      // 32768
#define CH    128                 // scan chunk length
#define NCH   (TLEN / CH)         // 32 chunks per batch

// Scratch (no allocations allowed -> device globals)
__device__ float g_Bbar[NDIM * IDIM];          // B * delta        [N,I]
__device__ float g_a[NDIM];                    // A_bar_state      [N]
__device__ float g_Bu[(size_t)BT * NDIM];      // Bu -> xs (8 MB)  [b,t,n]
__device__ float g_end[BATCH * NCH * NDIM];    // chunk-local end states
__device__ float g_carry[BATCH * NCH * NDIM];  // chunk carry-in states

// ---------------------------------------------------------------------------
// K0: compute delta=softplus(log_delta), B_bar = B*delta, a_n = mean_i exp(delta_i*A_n)
// one block per n
// ---------------------------------------------------------------------------
__global__ void k_setup(const float* __restrict__ logA,
                        const float* __restrict__ B,
                        const float* __restrict__ logdelta) {
    int n = blockIdx.x;
    float A = -expf(logA[n]);
    __shared__ float red[256];
    float s = 0.f;
    for (int i = threadIdx.x; i < IDIM; i += 256) {
        float ld = logdelta[i];
        float d  = (ld > 20.f) ? ld : log1pf(expf(ld));   // softplus
        g_Bbar[n * IDIM + i] = B[n * IDIM + i] * d;
        s += expf(d * A);
    }
    red[threadIdx.x] = s;
    __syncthreads();
    for (int o = 128; o > 0; o >>= 1) {
        if (threadIdx.x < o) red[threadIdx.x] += red[threadIdx.x + o];
        __syncthreads();
    }
    if (threadIdx.x == 0) g_a[n] = red[0] * (1.f / IDIM);
}

// ---------------------------------------------------------------------------
// K1: GEMM1  Bu[bt,n] = sum_i Bbar[n,i] * u[bt,i]
// BM=128 (bt), BN=64 (all n), BK=16.  256 threads, 8x4 outputs per thread.
// ---------------------------------------------------------------------------
__global__ __launch_bounds__(256) void k_gemm1(const float* __restrict__ u) {
    __shared__ float u_s[16][132];   // [k][row], padded
    __shared__ float b_s[16][68];    // [k][n],  padded
    const int m0  = blockIdx.x * 128;
    const int tid = threadIdx.x;
    const int tx  = tid & 15;        // 16 col-groups (n)
    const int ty  = tid >> 4;        // 16 row-groups (bt)

    float acc[8][4];
#pragma unroll
    for (int j = 0; j < 8; j++)
#pragma unroll
        for (int c = 0; c < 4; c++) acc[j][c] = 0.f;

    for (int k0 = 0; k0 < IDIM; k0 += 16) {
        // u tile: 128 rows x 16 k  (512 float4, 2 per thread)
#pragma unroll
        for (int q = 0; q < 2; q++) {
            int idx = tid + 256 * q;
            int row = idx >> 2;
            int kk  = (idx & 3) << 2;
            float4 v = *reinterpret_cast<const float4*>(
                &u[(size_t)(m0 + row) * IDIM + k0 + kk]);
            u_s[kk + 0][row] = v.x; u_s[kk + 1][row] = v.y;
            u_s[kk + 2][row] = v.z; u_s[kk + 3][row] = v.w;
        }
        // Bbar tile: 64 n x 16 k  (256 float4, 1 per thread)
        {
            int n  = tid >> 2;
            int kk = (tid & 3) << 2;
            float4 v = *reinterpret_cast<const float4*>(
                &g_Bbar[n * IDIM + k0 + kk]);
            b_s[kk + 0][n] = v.x; b_s[kk + 1][n] = v.y;
            b_s[kk + 2][n] = v.z; b_s[kk + 3][n] = v.w;
        }
        __syncthreads();
#pragma unroll
        for (int kk = 0; kk < 16; kk++) {
            float4 a0 = *reinterpret_cast<const float4*>(&u_s[kk][ty * 8 + 0]);
            float4 a1 = *reinterpret_cast<const float4*>(&u_s[kk][ty * 8 + 4]);
            float4 b0 = *reinterpret_cast<const float4*>(&b_s[kk][tx * 4]);
            float av[8] = {a0.x, a0.y, a0.z, a0.w, a1.x, a1.y, a1.z, a1.w};
            float bv[4] = {b0.x, b0.y, b0.z, b0.w};
#pragma unroll
            for (int j = 0; j < 8; j++)
#pragma unroll
                for (int c = 0; c < 4; c++) acc[j][c] += av[j] * bv[c];
        }
        __syncthreads();
    }
#pragma unroll
    for (int j = 0; j < 8; j++) {
        float4 v = make_float4(acc[j][0], acc[j][1], acc[j][2], acc[j][3]);
        *reinterpret_cast<float4*>(
            &g_Bu[(size_t)(m0 + ty * 8 + j) * NDIM + tx * 4]) = v;
    }
}

// ---------------------------------------------------------------------------
// K2a: chunk-local scan (x0 = 0), in place on g_Bu; record chunk end state.
// one block per (batch, chunk); 64 threads = one per state n.
// ---------------------------------------------------------------------------
__global__ void k_scan_local() {
    int b  = blockIdx.x / NCH;
    int ch = blockIdx.x % NCH;
    int n  = threadIdx.x;
    float a = g_a[n];
    float x = 0.f;
    size_t base = ((size_t)b * TLEN + (size_t)ch * CH) * NDIM + n;
#pragma unroll 4
    for (int j = 0; j < CH; j++) {
        float v = g_Bu[base + (size_t)j * NDIM];
        x = x * a + v;
        g_Bu[base + (size_t)j * NDIM] = x;
    }
    g_end[(b * NCH + ch) * NDIM + n] = x;
}

// ---------------------------------------------------------------------------
// K2b: serial carry scan over chunks. 512 threads = (batch, n) pairs.
// ---------------------------------------------------------------------------
__global__ void k_carry() {
    int t = threadIdx.x;            // 0..511
    int b = t >> 6;
    int n = t & 63;
    float a  = g_a[n];
    float aL = a;
#pragma unroll
    for (int q = 0; q < 7; q++) aL *= aL;   // a^128 = a^CH
    float carry = 0.f;
    for (int c = 0; c < NCH; c++) {
        g_carry[(b * NCH + c) * NDIM + n] = carry;
        carry = carry * aL + g_end[(b * NCH + c) * NDIM + n];
    }
}

// ---------------------------------------------------------------------------
// K2c: apply carries: x[t0+j] += carry * a^(j+1)
// ---------------------------------------------------------------------------
__global__ void k_fixup() {
    int b  = blockIdx.x / NCH;
    int ch = blockIdx.x % NCH;
    if (ch == 0) return;            // carry is exactly 0
    int n  = threadIdx.x;
    float a = g_a[n];
    float c = g_carry[(b * NCH + ch) * NDIM + n];
    size_t base = ((size_t)b * TLEN + (size_t)ch * CH) * NDIM + n;
#pragma unroll 4
    for (int j = 0; j < CH; j++) {
        c *= a;
        g_Bu[base + (size_t)j * NDIM] += c;
    }
}

// ---------------------------------------------------------------------------
// K3: GEMM2 + residual:  y[bt,i] = sum_n C[i,n]*xs[bt,n] + D[i]*u[bt,i]
// BM=128 (bt), BN=128 (i), BK=32.  256 threads, 8x8 outputs per thread.
// ---------------------------------------------------------------------------
__global__ __launch_bounds__(256) void k_gemm2(const float* __restrict__ u,
                                               const float* __restrict__ C,
                                               const float* __restrict__ D,
                                               float* __restrict__ y) {
    __shared__ float x_s[32][132];   // [n][row]
    __shared__ float c_s[32][132];   // [n][i]
    const int m0  = blockIdx.x * 128;
    const int i0  = blockIdx.y * 128;
    const int tid = threadIdx.x;
    const int tx  = tid & 15;
    const int ty  = tid >> 4;

    float acc[8][8];
#pragma unroll
    for (int j = 0; j < 8; j++)
#pragma unroll
        for (int c = 0; c < 8; c++) acc[j][c] = 0.f;

    for (int k0 = 0; k0 < NDIM; k0 += 32) {
        // xs tile: 128 rows x 32 n  (1024 float4, 4 per thread)
#pragma unroll
        for (int q = 0; q < 4; q++) {
            int idx = tid + 256 * q;
            int row = idx >> 3;
            int kk  = (idx & 7) << 2;
            float4 v = *reinterpret_cast<const float4*>(
                &g_Bu[(size_t)(m0 + row) * NDIM + k0 + kk]);
            x_s[kk + 0][row] = v.x; x_s[kk + 1][row] = v.y;
            x_s[kk + 2][row] = v.z; x_s[kk + 3][row] = v.w;
        }
        // C tile: 128 i x 32 n
#pragma unroll
        for (int q = 0; q < 4; q++) {
            int idx = tid + 256 * q;
            int i  = idx >> 3;
            int kk = (idx & 7) << 2;
            float4 v = *reinterpret_cast<const float4*>(
                &C[(size_t)(i0 + i) * NDIM + k0 + kk]);
            c_s[kk + 0][i] = v.x; c_s[kk + 1][i] = v.y;
            c_s[kk + 2][i] = v.z; c_s[kk + 3][i] = v.w;
        }
        __syncthreads();
#pragma unroll
        for (int kk = 0; kk < 32; kk++) {
            float4 a0 = *reinterpret_cast<const float4*>(&x_s[kk][ty * 8 + 0]);
            float4 a1 = *reinterpret_cast<const float4*>(&x_s[kk][ty * 8 + 4]);
            float4 b0 = *reinterpret_cast<const float4*>(&c_s[kk][tx * 8 + 0]);
            float4 b1 = *reinterpret_cast<const float4*>(&c_s[kk][tx * 8 + 4]);
            float av[8] = {a0.x, a0.y, a0.z, a0.w, a1.x, a1.y, a1.z, a1.w};
            float bv[8] = {b0.x, b0.y, b0.z, b0.w, b1.x, b1.y, b1.z, b1.w};
#pragma unroll
            for (int j = 0; j < 8; j++)
#pragma unroll
                for (int c = 0; c < 8; c++) acc[j][c] += av[j] * bv[c];
        }
        __syncthreads();
    }

    // epilogue: + D * u, vectorized
#pragma unroll
    for (int j = 0; j < 8; j++) {
        int row = m0 + ty * 8 + j;
#pragma unroll
        for (int cq = 0; cq < 2; cq++) {
            int col = i0 + tx * 8 + cq * 4;
            float4 uv = *reinterpret_cast<const float4*>(&u[(size_t)row * IDIM + col]);
            float4 dv = *reinterpret_cast<const float4*>(&D[col]);
            float4 o;
            o.x = acc[j][cq * 4 + 0] + dv.x * uv.x;
            o.y = acc[j][cq * 4 + 1] + dv.y * uv.y;
            o.z = acc[j][cq * 4 + 2] + dv.z * uv.z;
            o.w = acc[j][cq * 4 + 3] + dv.w * uv.w;
            *reinterpret_cast<float4*>(&y[(size_t)row * IDIM + col]) = o;
        }
    }
}

// ---------------------------------------------------------------------------
extern "C" void kernel_launch(void* const* d_in, const int* in_sizes, int n_in,
                              void* d_out, int out_size) {
    const float* u        = (const float*)d_in[0];
    const float* logA     = (const float*)d_in[1];
    const float* B        = (const float*)d_in[2];
    const float* C        = (const float*)d_in[3];
    const float* D        = (const float*)d_in[4];
    const float* logdelta = (const float*)d_in[5];
    float* y = (float*)d_out;

    k_setup<<<NDIM, 256>>>(logA, B, logdelta);
    k_gemm1<<<BT / 128, 256>>>(u);
    k_scan_local<<<BATCH * NCH, NDIM>>>();
    k_carry<<<1, BATCH * NDIM>>>();
    k_fixup<<<BATCH * NCH, NDIM>>>();
    dim3 g2(BT / 128, IDIM / 128);
    k_gemm2<<<g2, 256>>>(u, C, D, y);
}

// round 4
// speedup vs baseline: 2.0682x; 2.0682x over previous
#include <cuda_runtime.h>
#include <cuda_bf16.h>
#include <mma.h>
#include <cstdint>

using namespace nvcuda;

// Problem dims (fixed)
#define BATCH 8
#define TLEN  4096
#define IDIM  1024
#define NDIM  64
#define BT    (BATCH * TLEN)      // 32768
#define CH    128                 // scan chunk length
#define NCH   (TLEN / CH)         // 32 chunks per batch

// ---------------------------------------------------------------------------
// Scratch (device globals; allocation forbidden)
// ---------------------------------------------------------------------------
__device__ __nv_bfloat16 g_Bb[NDIM * IDIM];    // Bbar bf16 [n][k]
__device__ __nv_bfloat16 g_Cb[IDIM * NDIM];    // C bf16 [i][n]
__device__ float g_a[NDIM];                    // A_bar_state
__device__ float g_Bu[(size_t)BT * NDIM];      // Bu -> xs (8 MB)
__device__ float g_end[BATCH * NCH * NDIM];    // chunk-local end states

// ---------------------------------------------------------------------------
// K0: delta=softplus(log_delta); Bbar = B*delta -> bf16; a_n = mean_i exp(d_i A_n)
// one block per n
// ---------------------------------------------------------------------------
__global__ void k_setup(const float* __restrict__ logA,
                        const float* __restrict__ B,
                        const float* __restrict__ logdelta) {
    int n = blockIdx.x;
    float A = -expf(logA[n]);
    __shared__ float red[256];
    float s = 0.f;
    for (int i = threadIdx.x; i < IDIM; i += 256) {
        float ld = logdelta[i];
        float d  = (ld > 20.f) ? ld : log1pf(expf(ld));
        g_Bb[n * IDIM + i] = __float2bfloat16_rn(B[n * IDIM + i] * d);
        s += expf(d * A);
    }
    red[threadIdx.x] = s;
    __syncthreads();
    for (int o = 128; o > 0; o >>= 1) {
        if (threadIdx.x < o) red[threadIdx.x] += red[threadIdx.x + o];
        __syncthreads();
    }
    if (threadIdx.x == 0) g_a[n] = red[0] * (1.f / IDIM);
}

// K0b: convert C to bf16
__global__ void k_convC(const float* __restrict__ C) {
    int idx = blockIdx.x * 256 + threadIdx.x;      // 16384 float4s
    float4 v = *reinterpret_cast<const float4*>(C + 4 * (size_t)idx);
    __nv_bfloat162 lo = __floats2bfloat162_rn(v.x, v.y);
    __nv_bfloat162 hi = __floats2bfloat162_rn(v.z, v.w);
    uint2 pk = make_uint2(*reinterpret_cast<unsigned*>(&lo),
                          *reinterpret_cast<unsigned*>(&hi));
    *reinterpret_cast<uint2*>(&g_Cb[4 * (size_t)idx]) = pk;
}

// ---------------------------------------------------------------------------
// K1: wmma GEMM1  Bu[m,n] = sum_k Bbar[n,k] * u[m,k]
// Block tile: M=128, N=64 (all n), K-chunk=64. 256 threads = 8 warps (4x2).
// ---------------------------------------------------------------------------
#define G1_LDA 72
__global__ __launch_bounds__(256) void k_gemm1(const float* __restrict__ u) {
    __shared__ __nv_bfloat16 As[128 * G1_LDA];
    __shared__ __nv_bfloat16 Bs[64 * G1_LDA];
    const int tid = threadIdx.x;
    const int wid = tid >> 5;
    const int wy  = wid >> 1;          // 0..3 -> m offset 32*wy
    const int wx  = wid & 1;           // 0..1 -> n offset 32*wx
    const int m0  = blockIdx.x * 128;

    wmma::fragment<wmma::accumulator, 16, 16, 16, float> acc[2][2];
#pragma unroll
    for (int a = 0; a < 2; a++)
#pragma unroll
        for (int b = 0; b < 2; b++) wmma::fill_fragment(acc[a][b], 0.f);

    for (int kc = 0; kc < IDIM; kc += 64) {
        __syncthreads();
        // u tile: 128 rows x 64 k fp32 -> bf16 (2048 float4, 8/thread)
#pragma unroll
        for (int q = 0; q < 8; q++) {
            int idx = tid + 256 * q;
            int row = idx >> 4;
            int k   = (idx & 15) << 2;
            float4 v = *reinterpret_cast<const float4*>(
                &u[(size_t)(m0 + row) * IDIM + kc + k]);
            __nv_bfloat162 lo = __floats2bfloat162_rn(v.x, v.y);
            __nv_bfloat162 hi = __floats2bfloat162_rn(v.z, v.w);
            uint2 pk = make_uint2(*reinterpret_cast<unsigned*>(&lo),
                                  *reinterpret_cast<unsigned*>(&hi));
            *reinterpret_cast<uint2*>(&As[row * G1_LDA + k]) = pk;
        }
        // Bbar tile: 64 n x 64 k bf16 (1024 uint2, 4/thread)
#pragma unroll
        for (int q = 0; q < 4; q++) {
            int idx = tid + 256 * q;
            int n   = idx >> 4;
            int k   = (idx & 15) << 2;
            uint2 pk = *reinterpret_cast<const uint2*>(&g_Bb[n * IDIM + kc + k]);
            *reinterpret_cast<uint2*>(&Bs[n * G1_LDA + k]) = pk;
        }
        __syncthreads();

#pragma unroll
        for (int ks = 0; ks < 4; ks++) {
            int k = ks * 16;
            wmma::fragment<wmma::matrix_a, 16, 16, 16, __nv_bfloat16, wmma::row_major> af[2];
            wmma::fragment<wmma::matrix_b, 16, 16, 16, __nv_bfloat16, wmma::col_major> bf[2];
#pragma unroll
            for (int mi = 0; mi < 2; mi++)
                wmma::load_matrix_sync(af[mi], &As[(wy * 32 + mi * 16) * G1_LDA + k], G1_LDA);
#pragma unroll
            for (int ni = 0; ni < 2; ni++)
                wmma::load_matrix_sync(bf[ni], &Bs[(wx * 32 + ni * 16) * G1_LDA + k], G1_LDA);
#pragma unroll
            for (int mi = 0; mi < 2; mi++)
#pragma unroll
                for (int ni = 0; ni < 2; ni++)
                    wmma::mma_sync(acc[mi][ni], af[mi], bf[ni], acc[mi][ni]);
        }
    }
#pragma unroll
    for (int mi = 0; mi < 2; mi++)
#pragma unroll
        for (int ni = 0; ni < 2; ni++)
            wmma::store_matrix_sync(
                &g_Bu[(size_t)(m0 + wy * 32 + mi * 16) * NDIM + wx * 32 + ni * 16],
                acc[mi][ni], NDIM, wmma::mem_row_major);
}

// ---------------------------------------------------------------------------
// K2a: chunk-local scan (in place on g_Bu), record chunk end state.
// ---------------------------------------------------------------------------
__global__ void k_scan_local() {
    int b  = blockIdx.x / NCH;
    int ch = blockIdx.x % NCH;
    int n  = threadIdx.x;
    float a = g_a[n];
    float x = 0.f;
    size_t base = ((size_t)b * TLEN + (size_t)ch * CH) * NDIM + n;
#pragma unroll 4
    for (int j = 0; j < CH; j++) {
        float v = g_Bu[base + (size_t)j * NDIM];
        x = x * a + v;
        g_Bu[base + (size_t)j * NDIM] = x;
    }
    g_end[(b * NCH + ch) * NDIM + n] = x;
}

// ---------------------------------------------------------------------------
// K2b: fused carry + fixup. Block (b,ch) computes its own carry from chunk
// ends (parallel loads) then applies carry * a^(j+1) to its chunk.
// ---------------------------------------------------------------------------
__global__ void k_carryfix() {
    int b  = blockIdx.x / NCH;
    int ch = blockIdx.x % NCH;
    if (ch == 0) return;
    int n  = threadIdx.x;
    float a  = g_a[n];
    float aL = a;
#pragma unroll
    for (int q = 0; q < 7; q++) aL *= aL;     // a^128
    float carry = 0.f;
    for (int c = 0; c < ch; c++)
        carry = carry * aL + g_end[(b * NCH + c) * NDIM + n];
    size_t base = ((size_t)b * TLEN + (size_t)ch * CH) * NDIM + n;
    float cc = carry;
#pragma unroll 4
    for (int j = 0; j < CH; j++) {
        cc *= a;
        g_Bu[base + (size_t)j * NDIM] += cc;
    }
}

// ---------------------------------------------------------------------------
// K3: wmma GEMM2 + residual: y[m,i] = sum_n C[i,n]*xs[m,n] + D[i]*u[m,i]
// Block tile: M=128, N(i)=128, K=64. 256 threads = 8 warps (4x2),
// warp tile 32(m) x 64(i). Staging in smem for the D*u epilogue.
// ---------------------------------------------------------------------------
#define G2_LDA 72
#define G2_LDY 132
#define G2_XS_OFF 0
#define G2_CS_OFF (128 * G2_LDA * 2)                       // 18432
#define G2_YS_OFF (G2_CS_OFF + 128 * G2_LDA * 2)           // 36864
#define G2_SMEM   (G2_YS_OFF + 128 * G2_LDY * 4)           // 104448

__global__ __launch_bounds__(256) void k_gemm2(const float* __restrict__ u,
                                               const float* __restrict__ D,
                                               float* __restrict__ y) {
    extern __shared__ char smem[];
    __nv_bfloat16* Xs = reinterpret_cast<__nv_bfloat16*>(smem + G2_XS_OFF);
    __nv_bfloat16* Cs = reinterpret_cast<__nv_bfloat16*>(smem + G2_CS_OFF);
    float*         Ys = reinterpret_cast<float*>(smem + G2_YS_OFF);

    const int tid = threadIdx.x;
    const int wid = tid >> 5;
    const int wy  = wid >> 1;          // 0..3 -> m offset 32*wy
    const int wx  = wid & 1;           // 0..1 -> i offset 64*wx
    const int m0  = blockIdx.x * 128;
    const int i0  = blockIdx.y * 128;

    // X tile: 128 rows x 64 n fp32 -> bf16 (2048 float4, 8/thread)
#pragma unroll
    for (int q = 0; q < 8; q++) {
        int idx = tid + 256 * q;
        int row = idx >> 4;
        int k   = (idx & 15) << 2;
        float4 v = *reinterpret_cast<const float4*>(&g_Bu[(size_t)(m0 + row) * NDIM + k]);
        __nv_bfloat162 lo = __floats2bfloat162_rn(v.x, v.y);
        __nv_bfloat162 hi = __floats2bfloat162_rn(v.z, v.w);
        uint2 pk = make_uint2(*reinterpret_cast<unsigned*>(&lo),
                              *reinterpret_cast<unsigned*>(&hi));
        *reinterpret_cast<uint2*>(&Xs[row * G2_LDA + k]) = pk;
    }
    // C tile: 128 i-rows x 64 n bf16 (2048 uint2, 8/thread)  [FIXED: q<8]
#pragma unroll
    for (int q = 0; q < 8; q++) {
        int idx = tid + 256 * q;
        int i   = idx >> 4;
        int k   = (idx & 15) << 2;
        uint2 pk = *reinterpret_cast<const uint2*>(&g_Cb[(size_t)(i0 + i) * NDIM + k]);
        *reinterpret_cast<uint2*>(&Cs[i * G2_LDA + k]) = pk;
    }
    __syncthreads();

    wmma::fragment<wmma::accumulator, 16, 16, 16, float> acc[2][4];
#pragma unroll
    for (int a = 0; a < 2; a++)
#pragma unroll
        for (int b = 0; b < 4; b++) wmma::fill_fragment(acc[a][b], 0.f);

#pragma unroll
    for (int ks = 0; ks < 4; ks++) {
        int k = ks * 16;
        wmma::fragment<wmma::matrix_a, 16, 16, 16, __nv_bfloat16, wmma::row_major> af[2];
        wmma::fragment<wmma::matrix_b, 16, 16, 16, __nv_bfloat16, wmma::col_major> bf[4];
#pragma unroll
        for (int mi = 0; mi < 2; mi++)
            wmma::load_matrix_sync(af[mi], &Xs[(wy * 32 + mi * 16) * G2_LDA + k], G2_LDA);
#pragma unroll
        for (int ni = 0; ni < 4; ni++)
            wmma::load_matrix_sync(bf[ni], &Cs[(wx * 64 + ni * 16) * G2_LDA + k], G2_LDA);
#pragma unroll
        for (int mi = 0; mi < 2; mi++)
#pragma unroll
            for (int ni = 0; ni < 4; ni++)
                wmma::mma_sync(acc[mi][ni], af[mi], bf[ni], acc[mi][ni]);
    }

    // stage accumulators to smem
#pragma unroll
    for (int mi = 0; mi < 2; mi++)
#pragma unroll
        for (int ni = 0; ni < 4; ni++)
            wmma::store_matrix_sync(&Ys[(wy * 32 + mi * 16) * G2_LDY + wx * 64 + ni * 16],
                                    acc[mi][ni], G2_LDY, wmma::mem_row_major);
    __syncthreads();

    // epilogue: y = Ys + D*u  (128x128 out tile, 16 float4/thread)
#pragma unroll
    for (int q = 0; q < 16; q++) {
        int idx = tid + 256 * q;
        int row = idx >> 5;
        int col = (idx & 31) << 2;
        int grow = m0 + row;
        int gcol = i0 + col;
        float4 uv = *reinterpret_cast<const float4*>(&u[(size_t)grow * IDIM + gcol]);
        float4 dv = *reinterpret_cast<const float4*>(&D[gcol]);
        float4 sv = *reinterpret_cast<const float4*>(&Ys[row * G2_LDY + col]);
        float4 o;
        o.x = sv.x + dv.x * uv.x;
        o.y = sv.y + dv.y * uv.y;
        o.z = sv.z + dv.z * uv.z;
        o.w = sv.w + dv.w * uv.w;
        *reinterpret_cast<float4*>(&y[(size_t)grow * IDIM + gcol]) = o;
    }
}

// ---------------------------------------------------------------------------
extern "C" void kernel_launch(void* const* d_in, const int* in_sizes, int n_in,
                              void* d_out, int out_size) {
    const float* u        = (const float*)d_in[0];
    const float* logA     = (const float*)d_in[1];
    const float* B        = (const float*)d_in[2];
    const float* C        = (const float*)d_in[3];
    const float* D        = (const float*)d_in[4];
    const float* logdelta = (const float*)d_in[5];
    float* y = (float*)d_out;

    cudaFuncSetAttribute(k_gemm2, cudaFuncAttributeMaxDynamicSharedMemorySize, G2_SMEM);

    k_setup<<<NDIM, 256>>>(logA, B, logdelta);
    k_convC<<<IDIM * NDIM / 1024, 256>>>(C);
    k_gemm1<<<BT / 128, 256>>>(u);
    k_scan_local<<<BATCH * NCH, NDIM>>>();
    k_carryfix<<<BATCH * NCH, NDIM>>>();
    dim3 g2(BT / 128, IDIM / 128);
    k_gemm2<<<g2, 256, G2_SMEM>>>(u, D, y);
}